// round 2
// baseline (speedup 1.0000x reference)
#include <cuda_runtime.h>
#include <cuda_bf16.h>
#include <math.h>

#define NN 20000
#define EE 640000
#define HH 128
#define NB 16

// ---------------- scratch ----------------
__device__ int   g_is64;
__device__ int   g_src[EE];
__device__ int   g_dst[EE];
__device__ float g_h[(size_t)NN * 256];      // concat(x[src], x[dst])
__device__ float g_t[(size_t)NN * 128];      // silu(h@W1+b1)
__device__ float g_e[(size_t)NN * 128];
__device__ float g_q[(size_t)NN * 128];
__device__ float g_k[(size_t)NN * 128];
__device__ float g_ev[(size_t)NN * 3];
__device__ float g_logit[EE];
__device__ int   g_srcs[EE];
__device__ unsigned char g_bin[EE];
__device__ int g_counts[NN];
__device__ int g_offs[NN + 1];
__device__ int g_cursor[NN];
__device__ int g_eids[EE];

// ---------------- helpers ----------------
__device__ __forceinline__ unsigned encf(float f) {
    unsigned u = __float_as_uint(f);
    return (u & 0x80000000u) ? ~u : (u | 0x80000000u);
}
__device__ __forceinline__ float decf(unsigned u) {
    u = (u & 0x80000000u) ? (u & 0x7fffffffu) : ~u;
    return __uint_as_float(u);
}

// ---------------- dtype detection + index normalization ----------------
// int64 little-endian with indices < 2^31  =>  odd 4-byte words are all zero.
// int32 uniform in [0,20000)               =>  P(64 odd words all zero) ~ 0.
__global__ void detect_kernel(const int* __restrict__ ei_raw) {
    int allzero = 1;
    #pragma unroll
    for (int i = 1; i < 128; i += 2)
        if (ei_raw[i] != 0) allzero = 0;
    g_is64 = allzero;
}

__global__ void normalize_idx_kernel(const void* __restrict__ ei_raw) {
    int i = blockIdx.x * blockDim.x + threadIdx.x;
    if (i >= EE) return;
    if (g_is64) {
        const long long* e = (const long long*)ei_raw;
        g_src[i] = (int)e[i];
        g_dst[i] = (int)e[(size_t)EE + i];
    } else {
        const int* e = (const int*)ei_raw;
        g_src[i] = e[i];
        g_dst[i] = e[EE + i];
    }
}

// ---------------- CSR build ----------------
__global__ void zero_counts_kernel() {
    int i = blockIdx.x * blockDim.x + threadIdx.x;
    if (i < NN) g_counts[i] = 0;
}

__global__ void count_dst_kernel() {
    int i = blockIdx.x * blockDim.x + threadIdx.x;
    if (i < EE) atomicAdd(&g_counts[g_dst[i]], 1);
}

__global__ void scan_offsets_kernel() {
    __shared__ int sh_carry;
    __shared__ int wsum[32];
    int tid = threadIdx.x, lane = tid & 31, wid = tid >> 5;
    if (tid == 0) sh_carry = 0;
    __syncthreads();
    for (int base = 0; base < NN; base += 1024) {
        int c0 = sh_carry;
        int i = base + tid;
        int v = (i < NN) ? g_counts[i] : 0;
        int x = v;
        #pragma unroll
        for (int off = 1; off < 32; off <<= 1) {
            int y = __shfl_up_sync(~0u, x, off);
            if (lane >= off) x += y;
        }
        if (lane == 31) wsum[wid] = x;
        __syncthreads();
        if (wid == 0) {
            int ws = wsum[lane];
            #pragma unroll
            for (int off = 1; off < 32; off <<= 1) {
                int y = __shfl_up_sync(~0u, ws, off);
                if (lane >= off) ws += y;
            }
            wsum[lane] = ws;
        }
        __syncthreads();
        int incl = c0 + x + (wid ? wsum[wid - 1] : 0);
        if (i < NN) { g_offs[i] = incl - v; g_cursor[i] = incl - v; }
        __syncthreads();
        if (tid == 1023) sh_carry = incl;
        __syncthreads();
    }
    if (threadIdx.x == 0) g_offs[NN] = sh_carry;
}

__global__ void scatter_edges_kernel() {
    int i = blockIdx.x * blockDim.x + threadIdx.x;
    if (i < EE) {
        int p = atomicAdd(&g_cursor[g_dst[i]], 1);
        g_eids[p] = i;
    }
}

// ---------------- geometry + gathers (first NN edge rows only) ----------------
__global__ void compute_ev_kernel(const float* __restrict__ pos) {
    int i = blockIdx.x * blockDim.x + threadIdx.x;
    if (i >= NN) return;
    int s = g_src[i];
    int d = g_dst[i];
    float vx = pos[d * 3 + 0] - pos[s * 3 + 0];
    float vy = pos[d * 3 + 1] - pos[s * 3 + 1];
    float vz = pos[d * 3 + 2] - pos[s * 3 + 2];
    float inv = 1.0f / (sqrtf(vx * vx + vy * vy + vz * vz) + 1e-8f);
    g_ev[i * 3 + 0] = vx * inv;
    g_ev[i * 3 + 1] = vy * inv;
    g_ev[i * 3 + 2] = vz * inv;
}

__global__ void gather_h_kernel(const float* __restrict__ x) {
    int idx = blockIdx.x * blockDim.x + threadIdx.x;
    if (idx >= NN * 64) return;
    int i = idx >> 6;
    int c = idx & 63;
    int node = (c < 32) ? g_src[i] : g_dst[i];
    const float4* x4 = (const float4*)x;
    float4* h4 = (float4*)g_h;
    h4[(size_t)i * 64 + c] = x4[(size_t)node * 32 + (c & 31)];
}

// ---------------- SIMT fp32 GEMM: C[M,128] = act(A[M,K] @ W[K,128] + bias) --------------
// BM=64, BN=128, BK=16, 256 threads, 4x8 register tile per thread.
__global__ __launch_bounds__(256) void gemm128_kernel(
    const float* __restrict__ A, const float* __restrict__ W,
    const float* __restrict__ bias, float* __restrict__ C,
    int M, int K, int act)
{
    __shared__ float As[16][68];
    __shared__ float Bs[16][128];
    int tid = threadIdx.x;
    int tr = tid / 16;           // 0..15
    int tc = tid % 16;           // 0..15
    int rowBase = blockIdx.x * 64;

    float acc[4][8];
    #pragma unroll
    for (int i = 0; i < 4; i++)
        #pragma unroll
        for (int j = 0; j < 8; j++) acc[i][j] = 0.f;

    int aRow  = tid / 4;          // 0..63
    int aCol4 = (tid % 4) * 4;    // 0,4,8,12
    int bRow  = tid / 16;         // 0..15
    int bCol  = (tid % 16) * 8;   // 0..120

    for (int kt = 0; kt < K; kt += 16) {
        int gm = rowBase + aRow;
        float4 av = make_float4(0.f, 0.f, 0.f, 0.f);
        if (gm < M) av = *(const float4*)(A + (size_t)gm * K + kt + aCol4);
        As[aCol4 + 0][aRow] = av.x;
        As[aCol4 + 1][aRow] = av.y;
        As[aCol4 + 2][aRow] = av.z;
        As[aCol4 + 3][aRow] = av.w;

        float4 bv0 = *(const float4*)(W + (size_t)(kt + bRow) * 128 + bCol);
        float4 bv1 = *(const float4*)(W + (size_t)(kt + bRow) * 128 + bCol + 4);
        *(float4*)&Bs[bRow][bCol]     = bv0;
        *(float4*)&Bs[bRow][bCol + 4] = bv1;
        __syncthreads();

        #pragma unroll
        for (int kk = 0; kk < 16; kk++) {
            float ra[4], rb[8];
            #pragma unroll
            for (int i = 0; i < 4; i++) ra[i] = As[kk][tr * 4 + i];
            #pragma unroll
            for (int j = 0; j < 8; j++) rb[j] = Bs[kk][tc * 8 + j];
            #pragma unroll
            for (int i = 0; i < 4; i++)
                #pragma unroll
                for (int j = 0; j < 8; j++) acc[i][j] += ra[i] * rb[j];
        }
        __syncthreads();
    }

    #pragma unroll
    for (int i = 0; i < 4; i++) {
        int gm = rowBase + tr * 4 + i;
        if (gm >= M) continue;
        #pragma unroll
        for (int j = 0; j < 8; j += 4) {
            float4 o;
            float* ov = &o.x;
            #pragma unroll
            for (int jj = 0; jj < 4; jj++) {
                float v = acc[i][j + jj] + bias[tc * 8 + j + jj];
                if (act) v = v / (1.f + expf(-v));   // silu
                ov[jj] = v;
            }
            *(float4*)(C + (size_t)gm * 128 + tc * 8 + j) = o;
        }
    }
}

// ---------------- per-node aggregation ----------------
// One 128-thread block per destination node n.
__global__ __launch_bounds__(128) void aggregate_kernel(float* __restrict__ out)
{
    int n = blockIdx.x;
    int tid = threadIdx.x;       // == h column
    int lane = tid & 31, wid = tid >> 5;

    __shared__ float qn[128];
    __shared__ float evn[3];
    __shared__ unsigned binMaxU[16];
    __shared__ float binMax[16];
    __shared__ float binSum[16];
    __shared__ float acc[16 * 128];

    qn[tid] = g_q[(size_t)n * 128 + tid];
    if (tid < 3) evn[tid] = g_ev[n * 3 + tid];
    if (tid < 16) { binMaxU[tid] = 0x007FFFFFu; /* enc(-inf) */ binSum[tid] = 0.f; }
    #pragma unroll
    for (int b = 0; b < 16; b++) acc[b * 128 + tid] = 0.f;
    __syncthreads();

    int o0 = g_offs[n];
    int deg = g_offs[n + 1] - o0;

    // pass 1: warp per edge — logits, bins, per-bin max
    for (int j = wid; j < deg; j += 4) {
        int pos = o0 + j;
        int eid = g_eids[pos];
        int s = g_src[eid];
        const float* ks = g_k + (size_t)s * 128;
        float d = 0.f;
        #pragma unroll
        for (int i = 0; i < 4; i++) d += qn[lane + 32 * i] * ks[lane + 32 * i];
        #pragma unroll
        for (int off = 16; off; off >>= 1) d += __shfl_xor_sync(~0u, d, off);
        if (lane == 0) {
            float lg = d * 0.08838834764831843f;   // 1/sqrt(128)
            float c = evn[0] * g_ev[s * 3 + 0] + evn[1] * g_ev[s * 3 + 1] + evn[2] * g_ev[s * 3 + 2];
            c = fminf(fmaxf(c, -1.f), 1.f);
            int cnt = 0;
            #pragma unroll
            for (int t = 0; t < 17; t++) cnt += ((-1.f + 0.125f * (float)t) < c) ? 1 : 0;
            int b = min(max(cnt - 1, 0), NB - 1);
            g_logit[pos] = lg;
            g_srcs[pos] = s;
            g_bin[pos] = (unsigned char)b;
            atomicMax(&binMaxU[b], encf(lg));
        }
    }
    __syncthreads();
    if (tid < 16) binMax[tid] = decf(binMaxU[tid]);
    __syncthreads();

    // pass 2: block-serial per edge, column-per-thread accumulation (race-free)
    for (int j = 0; j < deg; j++) {
        int pos = o0 + j;
        float lg = g_logit[pos];
        int b = (int)g_bin[pos];
        int s = g_srcs[pos];
        float ex = expf(lg - binMax[b]);
        acc[b * 128 + tid] += ex * g_e[(size_t)s * 128 + tid];
        if (tid == 0) binSum[b] += ex;
    }
    __syncthreads();

    float inv[16];
    #pragma unroll
    for (int b = 0; b < 16; b++) inv[b] = 1.f / (binSum[b] + 1e-16f);

    // out[n, h*16 + b] = acc[b][h] * inv[b]
    float4* o4 = (float4*)(out + (size_t)n * (HH * NB) + tid * NB);
    #pragma unroll
    for (int g = 0; g < 4; g++) {
        float4 v;
        v.x = acc[(g * 4 + 0) * 128 + tid] * inv[g * 4 + 0];
        v.y = acc[(g * 4 + 1) * 128 + tid] * inv[g * 4 + 1];
        v.z = acc[(g * 4 + 2) * 128 + tid] * inv[g * 4 + 2];
        v.w = acc[(g * 4 + 3) * 128 + tid] * inv[g * 4 + 3];
        o4[g] = v;
    }
}

// ---------------- launcher ----------------
extern "C" void kernel_launch(void* const* d_in, const int* in_sizes, int n_in,
                              void* d_out, int out_size) {
    const float*     x   = (const float*)d_in[0];
    const float*     pos = (const float*)d_in[1];
    const void*      ei  = (const void*)d_in[2];   // int32 or int64, detected on device
    const float*     W1  = (const float*)d_in[3];
    const float*     b1  = (const float*)d_in[4];
    const float*     W2  = (const float*)d_in[5];
    const float*     b2  = (const float*)d_in[6];
    const float*     Wq  = (const float*)d_in[7];
    const float*     bq  = (const float*)d_in[8];
    const float*     Wk  = (const float*)d_in[9];
    const float*     bk  = (const float*)d_in[10];
    // d_in[11], d_in[12] = Wv, bv — unused by the reference output
    float* out = (float*)d_out;

    float *ph, *pt, *pe, *pq, *pk;
    cudaGetSymbolAddress((void**)&ph, g_h);
    cudaGetSymbolAddress((void**)&pt, g_t);
    cudaGetSymbolAddress((void**)&pe, g_e);
    cudaGetSymbolAddress((void**)&pq, g_q);
    cudaGetSymbolAddress((void**)&pk, g_k);

    // index dtype detection + normalization to int32
    detect_kernel<<<1, 1>>>((const int*)ei);
    normalize_idx_kernel<<<(EE + 255) / 256, 256>>>(ei);

    // CSR by destination node
    zero_counts_kernel<<<(NN + 255) / 256, 256>>>();
    count_dst_kernel<<<(EE + 255) / 256, 256>>>();
    scan_offsets_kernel<<<1, 1024>>>();
    scatter_edges_kernel<<<(EE + 255) / 256, 256>>>();

    // tables over the first NN edge rows only (the PyG gather shortcut)
    compute_ev_kernel<<<(NN + 255) / 256, 256>>>(pos);
    gather_h_kernel<<<(NN * 64 + 255) / 256, 256>>>(x);
    gemm128_kernel<<<(NN + 63) / 64, 256>>>(ph, W1, b1, pt, NN, 256, 1);
    gemm128_kernel<<<(NN + 63) / 64, 256>>>(pt, W2, b2, pe, NN, 128, 0);
    gemm128_kernel<<<(NN + 63) / 64, 256>>>(pe, Wq, bq, pq, NN, 128, 0);
    gemm128_kernel<<<(NN + 63) / 64, 256>>>(pe, Wk, bk, pk, NN, 128, 0);

    // per-node grouped softmax + weighted scatter
    aggregate_kernel<<<NN, 128>>>(out);
}